// round 5
// baseline (speedup 1.0000x reference)
#include <cuda_runtime.h>
#include <math.h>

#define NN 12000
#define EE 400000

// ---------------- scratch (static device globals; no allocation) ----------------
__device__ int   d_is64;           // 1 if edge_index is int64, 0 if int32
__device__ int   d_cnt_src[NN];
__device__ int   d_cnt_dst[NN];
__device__ int   d_rp_src[NN + 1];
__device__ int   d_rp_dst[NN + 1];
__device__ int   d_cur_src[NN];
__device__ int   d_cur_dst[NN];
__device__ int   d_nb_src[EE];     // neighbors (dst) grouped by src, self-edges excluded
__device__ int   d_nb_dst[EE];     // neighbors (src) grouped by dst, all edges
__device__ float d_dis[NN];        // dense-path  deg^-1/2
__device__ float d_dinv[NN];       // sparse-path deg^-1/2
__device__ __align__(16) float d_bufA[NN * 128];
__device__ __align__(16) float d_bufB[NN * 128];
__device__ __align__(16) float d_g[NN * 8];   // L5 pre-agg logits, padded stride 8

static inline int cdiv(int a, int b) { return (a + b - 1) / b; }

// compile-time buffer selection (device globals referenced from device code only)
template<int SEL>
__device__ __forceinline__ float* buf_ptr() {
    if (SEL == 1) return d_bufA;
    return d_bufB;
}

// ---------------- zero counts + edge dtype detection (merged) ----------------
// Block 0 additionally probes the edge dtype: view edges as int32 words; the
// first 800000 words are in-bounds for either dtype. If really int64 (values
// < 2^31), every odd word is a zero high-word.
__global__ void k_zero_detect(const int* __restrict__ e32) {
    int i = blockIdx.x * blockDim.x + threadIdx.x;
    if (i < NN) { d_cnt_src[i] = 0; d_cnt_dst[i] = 0; }
    if (blockIdx.x == 0) {
        __shared__ int any_nonzero;
        if (threadIdx.x == 0) any_nonzero = 0;
        __syncthreads();
        int nz = 0;
        for (int k = threadIdx.x; k < 4096; k += blockDim.x)
            if (e32[2 * k + 1] != 0) nz = 1;
        if (nz) any_nonzero = 1;
        __syncthreads();
        if (threadIdx.x == 0) d_is64 = any_nonzero ? 0 : 1;
    }
}

__device__ __forceinline__ void load_edge(const int* __restrict__ e32, int e, int& s, int& d) {
    if (d_is64) { s = e32[2 * e]; d = e32[2 * (EE + e)]; }
    else        { s = e32[e];     d = e32[EE + e]; }
}

// ---------------- CSR build ----------------
__global__ void k_count(const int* __restrict__ e32) {
    int e = blockIdx.x * blockDim.x + threadIdx.x;
    if (e >= EE) return;
    int s, d;
    load_edge(e32, e, s, d);
    if ((unsigned)s >= NN || (unsigned)d >= NN) return;
    atomicAdd(&d_cnt_dst[d], 1);
    if (s != d) atomicAdd(&d_cnt_src[s], 1);
}

// single-block scan, 1024 threads, 12 contiguous elements per thread.
// Warp-shuffle scan of per-thread sums; 4 syncs per pass instead of ~120.
__global__ void k_scan() {
    __shared__ int wsum[32];
    constexpr int CH = 12;  // 1024 * 12 = 12288 >= NN
    int t = threadIdx.x;
    int lane = t & 31, wid = t >> 5;
    for (int which = 0; which < 2; which++) {
        const int* cnt = which ? d_cnt_dst : d_cnt_src;
        int* rp  = which ? d_rp_dst  : d_rp_src;
        int* cur = which ? d_cur_dst : d_cur_src;
        float* nrm = which ? d_dinv : d_dis;

        int base = t * CH;
        int v[CH];
        int s = 0;
#pragma unroll
        for (int k = 0; k < CH; k++) {
            int i = base + k;
            int x = (i < NN) ? cnt[i] : 0;
            v[k] = x; s += x;
        }
        // inclusive warp scan of per-thread sums
        int sc = s;
#pragma unroll
        for (int off = 1; off < 32; off <<= 1) {
            int y = __shfl_up_sync(0xFFFFFFFFu, sc, off);
            if (lane >= off) sc += y;
        }
        if (lane == 31) wsum[wid] = sc;
        __syncthreads();
        if (wid == 0) {
            int ws = wsum[lane];
#pragma unroll
            for (int off = 1; off < 32; off <<= 1) {
                int y = __shfl_up_sync(0xFFFFFFFFu, ws, off);
                if (lane >= off) ws += y;
            }
            wsum[lane] = ws;
        }
        __syncthreads();
        int run = sc - s + (wid > 0 ? wsum[wid - 1] : 0);  // exclusive prefix for this thread
#pragma unroll
        for (int k = 0; k < CH; k++) {
            int i = base + k;
            if (i < NN) {
                nrm[i] = rsqrtf((float)(v[k] + 1));  // +1: diag=1 (dense) / self loop (sparse)
                cur[i] = run;
                run += v[k];
                rp[i + 1] = run;
            }
        }
        if (t == 0) rp[0] = 0;
        __syncthreads();  // protect wsum reuse in next pass
    }
}

__global__ void k_fill(const int* __restrict__ e32) {
    int e = blockIdx.x * blockDim.x + threadIdx.x;
    if (e >= EE) return;
    int s, d;
    load_edge(e32, e, s, d);
    if ((unsigned)s >= NN || (unsigned)d >= NN) return;
    int p = atomicAdd(&d_cur_dst[d], 1);
    d_nb_dst[p] = s;
    if (s != d) {
        int q = atomicAdd(&d_cur_src[s], 1);
        d_nb_src[q] = d;
    }
}

// ---------------- GEMM: Y = X[N,DIN] @ W[DIN,DOUT] (+bias, +relu) ----------------
// IN_SEL: 0 = external pointer arg, 1 = d_bufA, 2 = d_bufB.  OUT_SEL: 1/2.
template<int DIN, int DOUT, int BM, bool RELU, bool BIAS, int IN_SEL, int OUT_SEL>
__global__ void k_gemm(const float* __restrict__ Xext, const float* __restrict__ W,
                       const float* __restrict__ bias) {
    const float* X = (IN_SEL == 0) ? Xext : (const float*)buf_ptr<IN_SEL>();
    float* Y = buf_ptr<OUT_SEL>();

    constexpr int BK = 16, TM = 4, TN = 4;
    constexpr int TX = DOUT / TN, TY = BM / TM;
    constexpr int NT = TX * TY;
    __shared__ __align__(16) float Xs[BM][BK + 1];
    __shared__ __align__(16) float Ws[BK][DOUT];

    int tx = threadIdx.x, ty = threadIdx.y;
    int tid = ty * TX + tx;
    int row0 = blockIdx.x * BM;

    float acc[TM][TN];
#pragma unroll
    for (int i = 0; i < TM; i++)
#pragma unroll
        for (int j = 0; j < TN; j++) acc[i][j] = 0.f;

    for (int k0 = 0; k0 < DIN; k0 += BK) {
        for (int idx = tid; idx < BM * BK; idx += NT) {
            int r = idx / BK, c = idx % BK;
            int gr = row0 + r;
            Xs[r][c] = (gr < NN) ? X[gr * DIN + k0 + c] : 0.f;
        }
        for (int idx = tid; idx < BK * DOUT; idx += NT) {
            int r = idx / DOUT, c = idx % DOUT;
            Ws[r][c] = W[(k0 + r) * DOUT + c];
        }
        __syncthreads();
#pragma unroll
        for (int kk = 0; kk < BK; kk++) {
            float a[TM];
#pragma unroll
            for (int i = 0; i < TM; i++) a[i] = Xs[ty * TM + i][kk];
            float4 wv = *reinterpret_cast<const float4*>(&Ws[kk][tx * TN]);
            float w[TN] = {wv.x, wv.y, wv.z, wv.w};
#pragma unroll
            for (int i = 0; i < TM; i++)
#pragma unroll
                for (int j = 0; j < TN; j++) acc[i][j] += a[i] * w[j];
        }
        __syncthreads();
    }
#pragma unroll
    for (int i = 0; i < TM; i++) {
        int gr = row0 + ty * TM + i;
        if (gr < NN) {
#pragma unroll
            for (int j = 0; j < TN; j++) {
                int c = tx * TN + j;
                float r = acc[i][j];
                if (BIAS) r += bias[c];
                if (RELU) r = fmaxf(r, 0.f);
                Y[gr * DOUT + c] = r;
            }
        }
    }
}

// ---------------- aggregation: warp per node, lane per V channels ----------------
// IN_SEL selects X (1=A, 2=B); output is the other buffer. DENSE selects CSR set.
template<int D, bool BIASRELU, int IN_SEL, bool DENSE>
__global__ void k_agg(const float* __restrict__ bias) {
    const float* X = buf_ptr<IN_SEL>();
    float* Y = buf_ptr<IN_SEL == 1 ? 2 : 1>();
    const int*   rp  = DENSE ? d_rp_src : d_rp_dst;
    const int*   nb  = DENSE ? d_nb_src : d_nb_dst;
    const float* nrm = DENSE ? d_dis    : d_dinv;

    constexpr int V = D / 32;  // 1, 2 or 4
    int gw = (blockIdx.x * blockDim.x + threadIdx.x) >> 5;
    int lane = threadIdx.x & 31;
    if (gw >= NN) return;

    float acc[V];
#pragma unroll
    for (int v = 0; v < V; v++) acc[v] = 0.f;

    int beg = rp[gw], end = rp[gw + 1];
    int p = beg;
    for (; p + 4 <= end; p += 4) {
        int j0 = nb[p], j1 = nb[p + 1], j2 = nb[p + 2], j3 = nb[p + 3];
        float n0 = nrm[j0], n1 = nrm[j1], n2 = nrm[j2], n3 = nrm[j3];
        if (V == 4) {
            float4 x0 = *(const float4*)&X[j0 * D + lane * 4];
            float4 x1 = *(const float4*)&X[j1 * D + lane * 4];
            float4 x2 = *(const float4*)&X[j2 * D + lane * 4];
            float4 x3 = *(const float4*)&X[j3 * D + lane * 4];
            acc[0] += n0 * x0.x + n1 * x1.x + n2 * x2.x + n3 * x3.x;
            acc[1] += n0 * x0.y + n1 * x1.y + n2 * x2.y + n3 * x3.y;
            acc[2] += n0 * x0.z + n1 * x1.z + n2 * x2.z + n3 * x3.z;
            acc[3] += n0 * x0.w + n1 * x1.w + n2 * x2.w + n3 * x3.w;
        } else if (V == 2) {
            float2 x0 = *(const float2*)&X[j0 * D + lane * 2];
            float2 x1 = *(const float2*)&X[j1 * D + lane * 2];
            float2 x2 = *(const float2*)&X[j2 * D + lane * 2];
            float2 x3 = *(const float2*)&X[j3 * D + lane * 2];
            acc[0] += n0 * x0.x + n1 * x1.x + n2 * x2.x + n3 * x3.x;
            acc[1] += n0 * x0.y + n1 * x1.y + n2 * x2.y + n3 * x3.y;
        } else {
            acc[0] += n0 * X[j0 * D + lane] + n1 * X[j1 * D + lane]
                    + n2 * X[j2 * D + lane] + n3 * X[j3 * D + lane];
        }
    }
    for (; p < end; p++) {
        int j = nb[p];
        float nj = nrm[j];
        if (V == 4) {
            float4 x = *(const float4*)&X[j * D + lane * 4];
            acc[0] += nj * x.x; acc[1] += nj * x.y; acc[2] += nj * x.z; acc[3] += nj * x.w;
        } else if (V == 2) {
            float2 x = *(const float2*)&X[j * D + lane * 2];
            acc[0] += nj * x.x; acc[1] += nj * x.y;
        } else {
            acc[0] += nj * X[j * D + lane];
        }
    }
    float ni = nrm[gw], ni2 = ni * ni;
#pragma unroll
    for (int v = 0; v < V; v++) {
        float r = ni * acc[v] + ni2 * X[gw * D + lane * V + v];
        if (BIASRELU) r = fmaxf(r + bias[lane * V + v], 0.f);
        Y[gw * D + lane * V + v] = r;
    }
}

// ---------------- L5 GEMM: warp per row, bufB[N,128] @ W[128,6] -> d_g (stride 8) ----------------
__global__ void k_gemm6(const float* __restrict__ W) {
    const float* X = d_bufB;
    int row = (blockIdx.x * blockDim.x + threadIdx.x) >> 5;
    int lane = threadIdx.x & 31;
    if (row >= NN) return;
    float acc[6] = {0.f, 0.f, 0.f, 0.f, 0.f, 0.f};
#pragma unroll
    for (int kb = 0; kb < 4; kb++) {
        int k = kb * 32 + lane;
        float x = X[row * 128 + k];
#pragma unroll
        for (int c = 0; c < 6; c++) acc[c] += x * W[k * 6 + c];
    }
#pragma unroll
    for (int c = 0; c < 6; c++) {
#pragma unroll
        for (int off = 16; off >= 1; off >>= 1)
            acc[c] += __shfl_xor_sync(0xFFFFFFFF, acc[c], off);
    }
    if (lane == 0) {
#pragma unroll
        for (int c = 0; c < 6; c++) d_g[row * 8 + c] = acc[c];
    }
}

// ---------------- final: sparse agg over 6 channels + bias + log_softmax ----------------
__global__ void k_final(const float* __restrict__ b2, float* __restrict__ out) {
    int i = blockIdx.x * blockDim.x + threadIdx.x;
    if (i >= NN) return;
    float a0 = 0, a1 = 0, a2 = 0, a3 = 0, a4 = 0, a5 = 0;
    int beg = d_rp_dst[i], end = d_rp_dst[i + 1];
    int p = beg;
    for (; p + 2 <= end; p += 2) {
        int j0 = d_nb_dst[p], j1 = d_nb_dst[p + 1];
        float n0 = d_dinv[j0], n1 = d_dinv[j1];
        float4 u0 = *(const float4*)&d_g[j0 * 8];
        float2 v0 = *(const float2*)&d_g[j0 * 8 + 4];
        float4 u1 = *(const float4*)&d_g[j1 * 8];
        float2 v1 = *(const float2*)&d_g[j1 * 8 + 4];
        a0 += n0 * u0.x + n1 * u1.x;  a1 += n0 * u0.y + n1 * u1.y;
        a2 += n0 * u0.z + n1 * u1.z;  a3 += n0 * u0.w + n1 * u1.w;
        a4 += n0 * v0.x + n1 * v1.x;  a5 += n0 * v0.y + n1 * v1.y;
    }
    for (; p < end; p++) {
        int j = d_nb_dst[p];
        float nj = d_dinv[j];
        float4 u = *(const float4*)&d_g[j * 8];
        float2 v = *(const float2*)&d_g[j * 8 + 4];
        a0 += nj * u.x; a1 += nj * u.y; a2 += nj * u.z;
        a3 += nj * u.w; a4 += nj * v.x; a5 += nj * v.y;
    }
    float ni = d_dinv[i], ni2 = ni * ni;
    float4 su = *(const float4*)&d_g[i * 8];
    float2 sv = *(const float2*)&d_g[i * 8 + 4];
    float r[6];
    r[0] = ni * a0 + ni2 * su.x + b2[0];
    r[1] = ni * a1 + ni2 * su.y + b2[1];
    r[2] = ni * a2 + ni2 * su.z + b2[2];
    r[3] = ni * a3 + ni2 * su.w + b2[3];
    r[4] = ni * a4 + ni2 * sv.x + b2[4];
    r[5] = ni * a5 + ni2 * sv.y + b2[5];
    float m = r[0];
#pragma unroll
    for (int c = 1; c < 6; c++) m = fmaxf(m, r[c]);
    float s = 0.f;
#pragma unroll
    for (int c = 0; c < 6; c++) s += expf(r[c] - m);
    float l = logf(s);
#pragma unroll
    for (int c = 0; c < 6; c++) out[i * 6 + c] = r[c] - m - l;
}

// ---------------- launch ----------------
// Resolve inputs by element count (robust to metadata ordering). For tied sizes
// (W1/W14 both 16384, b13/b14 both 128) take k-th occurrence.
static int idx_of(const int* in_sizes, int n_in, int size, int ordinal) {
    int c = 0;
    for (int i = 0; i < n_in; i++) {
        if (in_sizes[i] == size) {
            if (c == ordinal) return i;
            c++;
        }
    }
    return 0;
}

extern "C" void kernel_launch(void* const* d_in, const int* in_sizes, int n_in,
                              void* d_out, int out_size) {
    const float* feats = (const float*)d_in[idx_of(in_sizes, n_in, NN * 512, 0)];
    const int*   e32   = (const int*)d_in[idx_of(in_sizes, n_in, 2 * EE, 0)];
    const float* W1  = (const float*)d_in[idx_of(in_sizes, n_in, 512 * 32, 0)];
    const float* b1  = (const float*)d_in[idx_of(in_sizes, n_in, 32, 0)];
    const float* W12 = (const float*)d_in[idx_of(in_sizes, n_in, 32 * 64, 0)];
    const float* b12 = (const float*)d_in[idx_of(in_sizes, n_in, 64, 0)];
    const float* W13 = (const float*)d_in[idx_of(in_sizes, n_in, 64 * 128, 0)];
    const float* b13 = (const float*)d_in[idx_of(in_sizes, n_in, 128, 0)];
    const float* W14 = (const float*)d_in[idx_of(in_sizes, n_in, 128 * 128, 1)];  // 2nd 16384
    const float* b14 = (const float*)d_in[idx_of(in_sizes, n_in, 128, 1)];        // 2nd 128
    const float* W2  = (const float*)d_in[idx_of(in_sizes, n_in, 128 * 6, 0)];
    const float* b2  = (const float*)d_in[idx_of(in_sizes, n_in, 6, 0)];
    float* out = (float*)d_out;

    // graph structure
    k_zero_detect<<<cdiv(NN, 256), 256>>>(e32);
    k_count<<<cdiv(EE, 256), 256>>>(e32);
    k_scan<<<1, 1024>>>();
    k_fill<<<cdiv(EE, 256), 256>>>(e32);

    // L1: bufA = feats@W1 (N,32); dense agg (A->B) + b1 + relu
    k_gemm<512, 32, 64, false, false, 0, 1><<<cdiv(NN, 64), dim3(8, 16)>>>(feats, W1, nullptr);
    k_agg<32, true, 1, true><<<cdiv(NN * 32, 256), 256>>>(b1);

    // L2: dense agg at 32 (B->A), then GEMM 32->64 (A->B) + b12 + relu
    k_agg<32, false, 2, true><<<cdiv(NN * 32, 256), 256>>>(nullptr);
    k_gemm<32, 64, 64, true, true, 1, 2><<<cdiv(NN, 64), dim3(16, 16)>>>(nullptr, W12, b12);

    // L3: sparse agg at 64 (B->A), then GEMM 64->128 (A->B) + b13 + relu
    k_agg<64, false, 2, false><<<cdiv(NN * 32, 256), 256>>>(nullptr);
    k_gemm<64, 128, 32, true, true, 1, 2><<<cdiv(NN, 32), dim3(32, 8)>>>(nullptr, W13, b13);

    // L4: sparse agg at 128 (B->A), then GEMM 128->128 (A->B) + b14 + relu
    k_agg<128, false, 2, false><<<cdiv(NN * 32, 256), 256>>>(nullptr);
    k_gemm<128, 128, 32, true, true, 1, 2><<<cdiv(NN, 32), dim3(32, 8)>>>(nullptr, W14, b14);

    // L5: GEMM 128->6 first (B -> d_g), then sparse agg at 6 + b2 + log_softmax
    k_gemm6<<<cdiv(NN * 32, 256), 256>>>(W2);
    k_final<<<cdiv(NN, 256), 256>>>(b2, out);
}

// round 7
// speedup vs baseline: 1.1136x; 1.1136x over previous
#include <cuda_runtime.h>
#include <math.h>

#define NN 12000
#define EE 400000

// ---------------- scratch (static device globals; no allocation) ----------------
// cnt arrays are zero at process start (static zero-init) and re-zeroed by
// k_scan after consumption, so every kernel_launch invocation sees zeros.
__device__ int   d_is64;           // 1 if edge_index is int64, 0 if int32
__device__ int   d_cnt_src[NN];
__device__ int   d_cnt_dst[NN];
__device__ int   d_rp_src[NN + 1];
__device__ int   d_rp_dst[NN + 1];
__device__ int   d_cur_src[NN];
__device__ int   d_cur_dst[NN];
__device__ int   d_nb_src[EE];     // neighbors (dst) grouped by src, self-edges excluded
__device__ int   d_nb_dst[EE];     // neighbors (src) grouped by dst, all edges
__device__ float d_dis[NN];        // dense-path  deg^-1/2
__device__ float d_dinv[NN];       // sparse-path deg^-1/2
__device__ __align__(16) float d_bufA[NN * 128];
__device__ __align__(16) float d_bufB[NN * 128];
__device__ __align__(16) float d_g[NN * 8];   // L5 pre-agg logits, padded stride 8

static inline int cdiv(int a, int b) { return (a + b - 1) / b; }

template<int SEL>
__device__ __forceinline__ float* buf_ptr() {
    if (SEL == 1) return d_bufA;
    return d_bufB;
}

// ---------------- edge dtype detection ----------------
// View edges as int32 words; first 800000 words are in-bounds for either dtype.
// If really int64 (values < 2^31), every odd word is a zero high-word.
__global__ void k_detect(const int* __restrict__ e32) {
    __shared__ int any_nonzero;
    if (threadIdx.x == 0) any_nonzero = 0;
    __syncthreads();
    int nz = 0;
    for (int k = threadIdx.x; k < 4096; k += blockDim.x)
        if (e32[2 * k + 1] != 0) nz = 1;
    if (nz) any_nonzero = 1;
    __syncthreads();
    if (threadIdx.x == 0) d_is64 = any_nonzero ? 0 : 1;
}

// ---------------- CSR build: 4 edges per thread for MLP ----------------
__global__ void k_count(const int* __restrict__ e32) {
    int base = (blockIdx.x * blockDim.x + threadIdx.x) * 4;
    int is64 = d_is64;
    int s[4], d[4];
#pragma unroll
    for (int k = 0; k < 4; k++) {
        int e = base + k;
        if (e < EE) {
            if (is64) { s[k] = e32[2 * e]; d[k] = e32[2 * (EE + e)]; }
            else      { s[k] = e32[e];     d[k] = e32[EE + e]; }
        } else { s[k] = -1; d[k] = -1; }
    }
#pragma unroll
    for (int k = 0; k < 4; k++) {
        if ((unsigned)d[k] < NN) atomicAdd(&d_cnt_dst[d[k]], 1);
        if ((unsigned)s[k] < NN && s[k] != d[k]) atomicAdd(&d_cnt_src[s[k]], 1);
    }
}

// single-block scan, 1024 threads, 12 contiguous elements per thread.
// Also re-zeroes cnt arrays (so the next replay starts clean).
__global__ void k_scan() {
    __shared__ int wsum[32];
    constexpr int CH = 12;  // 1024 * 12 = 12288 >= NN
    int t = threadIdx.x;
    int lane = t & 31, wid = t >> 5;
    for (int which = 0; which < 2; which++) {
        int* cnt = which ? d_cnt_dst : d_cnt_src;
        int* rp  = which ? d_rp_dst  : d_rp_src;
        int* cur = which ? d_cur_dst : d_cur_src;
        float* nrm = which ? d_dinv : d_dis;

        int base = t * CH;
        int v[CH];
        int s = 0;
#pragma unroll
        for (int k = 0; k < CH; k++) {
            int i = base + k;
            int x = (i < NN) ? cnt[i] : 0;
            if (i < NN) cnt[i] = 0;    // re-zero for next invocation
            v[k] = x; s += x;
        }
        int sc = s;
#pragma unroll
        for (int off = 1; off < 32; off <<= 1) {
            int y = __shfl_up_sync(0xFFFFFFFFu, sc, off);
            if (lane >= off) sc += y;
        }
        if (lane == 31) wsum[wid] = sc;
        __syncthreads();
        if (wid == 0) {
            int ws = wsum[lane];
#pragma unroll
            for (int off = 1; off < 32; off <<= 1) {
                int y = __shfl_up_sync(0xFFFFFFFFu, ws, off);
                if (lane >= off) ws += y;
            }
            wsum[lane] = ws;
        }
        __syncthreads();
        int run = sc - s + (wid > 0 ? wsum[wid - 1] : 0);
#pragma unroll
        for (int k = 0; k < CH; k++) {
            int i = base + k;
            if (i < NN) {
                nrm[i] = rsqrtf((float)(v[k] + 1));  // +1: diag=1 (dense) / self loop (sparse)
                cur[i] = run;
                run += v[k];
                rp[i + 1] = run;
            }
        }
        if (t == 0) rp[0] = 0;
        __syncthreads();
    }
}

__global__ void k_fill(const int* __restrict__ e32) {
    int base = (blockIdx.x * blockDim.x + threadIdx.x) * 4;
    int is64 = d_is64;
    int s[4], d[4];
#pragma unroll
    for (int k = 0; k < 4; k++) {
        int e = base + k;
        if (e < EE) {
            if (is64) { s[k] = e32[2 * e]; d[k] = e32[2 * (EE + e)]; }
            else      { s[k] = e32[e];     d[k] = e32[EE + e]; }
        } else { s[k] = -1; d[k] = -1; }
    }
    int p[4], q[4];
#pragma unroll
    for (int k = 0; k < 4; k++) {
        p[k] = ((unsigned)d[k] < NN) ? atomicAdd(&d_cur_dst[d[k]], 1) : -1;
        q[k] = ((unsigned)s[k] < NN && s[k] != d[k]) ? atomicAdd(&d_cur_src[s[k]], 1) : -1;
    }
#pragma unroll
    for (int k = 0; k < 4; k++) {
        if (p[k] >= 0) d_nb_dst[p[k]] = s[k];
        if (q[k] >= 0) d_nb_src[q[k]] = d[k];
    }
}

// ---------------- GEMM: Y = X[N,DIN] @ W[DIN,DOUT] (+bias, +relu) ----------------
// IN_SEL: 0 = external pointer arg, 1 = d_bufA, 2 = d_bufB.  OUT_SEL: 1/2.
template<int DIN, int DOUT, int BM, int BK, bool RELU, bool BIAS, int IN_SEL, int OUT_SEL>
__global__ void k_gemm(const float* __restrict__ Xext, const float* __restrict__ W,
                       const float* __restrict__ bias) {
    const float* X = (IN_SEL == 0) ? Xext : (const float*)buf_ptr<IN_SEL>();
    float* Y = buf_ptr<OUT_SEL>();

    constexpr int TM = 4, TN = 4;
    constexpr int TX = DOUT / TN, TY = BM / TM;
    constexpr int NT = TX * TY;
    static_assert(BK % 4 == 0, "");
    __shared__ float Xs[BM][BK + 1];
    __shared__ __align__(16) float Ws[BK][DOUT];

    int tx = threadIdx.x, ty = threadIdx.y;
    int tid = ty * TX + tx;
    int row0 = blockIdx.x * BM;

    float acc[TM][TN];
#pragma unroll
    for (int i = 0; i < TM; i++)
#pragma unroll
        for (int j = 0; j < TN; j++) acc[i][j] = 0.f;

    for (int k0 = 0; k0 < DIN; k0 += BK) {
        // stage X with float4 global loads
        constexpr int XF4 = BM * BK / 4;
#pragma unroll
        for (int idx = tid; idx < XF4; idx += NT) {
            int r = idx / (BK / 4), c4 = idx % (BK / 4);
            int gr = row0 + r;
            float4 xv = make_float4(0.f, 0.f, 0.f, 0.f);
            if (gr < NN) xv = *reinterpret_cast<const float4*>(&X[gr * DIN + k0 + c4 * 4]);
            Xs[r][c4 * 4 + 0] = xv.x;
            Xs[r][c4 * 4 + 1] = xv.y;
            Xs[r][c4 * 4 + 2] = xv.z;
            Xs[r][c4 * 4 + 3] = xv.w;
        }
        constexpr int WF4 = BK * DOUT / 4;
#pragma unroll
        for (int idx = tid; idx < WF4; idx += NT) {
            int r = idx / (DOUT / 4), c4 = idx % (DOUT / 4);
            *reinterpret_cast<float4*>(&Ws[r][c4 * 4]) =
                *reinterpret_cast<const float4*>(&W[(k0 + r) * DOUT + c4 * 4]);
        }
        __syncthreads();
#pragma unroll
        for (int kk = 0; kk < BK; kk++) {
            float a[TM];
#pragma unroll
            for (int i = 0; i < TM; i++) a[i] = Xs[ty * TM + i][kk];
            float4 wv = *reinterpret_cast<const float4*>(&Ws[kk][tx * TN]);
            float w[TN] = {wv.x, wv.y, wv.z, wv.w};
#pragma unroll
            for (int i = 0; i < TM; i++)
#pragma unroll
                for (int j = 0; j < TN; j++) acc[i][j] += a[i] * w[j];
        }
        __syncthreads();
    }
#pragma unroll
    for (int i = 0; i < TM; i++) {
        int gr = row0 + ty * TM + i;
        if (gr < NN) {
#pragma unroll
            for (int j = 0; j < TN; j++) {
                int c = tx * TN + j;
                float r = acc[i][j];
                if (BIAS) r += bias[c];
                if (RELU) r = fmaxf(r, 0.f);
                Y[gr * DOUT + c] = r;
            }
        }
    }
}

// ---------------- aggregation: warp per node, lane per V channels, unroll 8 ----------------
template<int D, bool BIASRELU, int IN_SEL, bool DENSE>
__global__ void k_agg(const float* __restrict__ bias) {
    const float* X = buf_ptr<IN_SEL>();
    float* Y = buf_ptr<IN_SEL == 1 ? 2 : 1>();
    const int*   rp  = DENSE ? d_rp_src : d_rp_dst;
    const int*   nb  = DENSE ? d_nb_src : d_nb_dst;
    const float* nrm = DENSE ? d_dis    : d_dinv;

    constexpr int V = D / 32;  // 1, 2 or 4
    int gw = (blockIdx.x * blockDim.x + threadIdx.x) >> 5;
    int lane = threadIdx.x & 31;
    if (gw >= NN) return;

    float acc[V];
#pragma unroll
    for (int v = 0; v < V; v++) acc[v] = 0.f;

    int beg = rp[gw], end = rp[gw + 1];
    int p = beg;
    constexpr int U = 8;
    for (; p + U <= end; p += U) {
        int j[U]; float n[U];
#pragma unroll
        for (int u = 0; u < U; u++) j[u] = nb[p + u];
#pragma unroll
        for (int u = 0; u < U; u++) n[u] = nrm[j[u]];
        if (V == 4) {
            float4 x[U];
#pragma unroll
            for (int u = 0; u < U; u++) x[u] = *(const float4*)&X[j[u] * D + lane * 4];
#pragma unroll
            for (int u = 0; u < U; u++) {
                acc[0] += n[u] * x[u].x; acc[1] += n[u] * x[u].y;
                acc[2] += n[u] * x[u].z; acc[3] += n[u] * x[u].w;
            }
        } else if (V == 2) {
            float2 x[U];
#pragma unroll
            for (int u = 0; u < U; u++) x[u] = *(const float2*)&X[j[u] * D + lane * 2];
#pragma unroll
            for (int u = 0; u < U; u++) { acc[0] += n[u] * x[u].x; acc[1] += n[u] * x[u].y; }
        } else {
            float x[U];
#pragma unroll
            for (int u = 0; u < U; u++) x[u] = X[j[u] * D + lane];
#pragma unroll
            for (int u = 0; u < U; u++) acc[0] += n[u] * x[u];
        }
    }
    for (; p < end; p++) {
        int j = nb[p];
        float nj = nrm[j];
        if (V == 4) {
            float4 x = *(const float4*)&X[j * D + lane * 4];
            acc[0] += nj * x.x; acc[1] += nj * x.y; acc[2] += nj * x.z; acc[3] += nj * x.w;
        } else if (V == 2) {
            float2 x = *(const float2*)&X[j * D + lane * 2];
            acc[0] += nj * x.x; acc[1] += nj * x.y;
        } else {
            acc[0] += nj * X[j * D + lane];
        }
    }
    float ni = nrm[gw], ni2 = ni * ni;
#pragma unroll
    for (int v = 0; v < V; v++) {
        float r = ni * acc[v] + ni2 * X[gw * D + lane * V + v];
        if (BIASRELU) r = fmaxf(r + bias[lane * V + v], 0.f);
        Y[gw * D + lane * V + v] = r;
    }
}

// ---------------- L5 GEMM: warp per row, bufB[N,128] @ W[128,6] -> d_g ----------------
__global__ void k_gemm6(const float* __restrict__ W) {
    const float* X = d_bufB;
    int row = (blockIdx.x * blockDim.x + threadIdx.x) >> 5;
    int lane = threadIdx.x & 31;
    if (row >= NN) return;
    float acc[6] = {0.f, 0.f, 0.f, 0.f, 0.f, 0.f};
#pragma unroll
    for (int kb = 0; kb < 4; kb++) {
        int k = kb * 32 + lane;
        float x = X[row * 128 + k];
#pragma unroll
        for (int c = 0; c < 6; c++) acc[c] += x * W[k * 6 + c];
    }
#pragma unroll
    for (int c = 0; c < 6; c++) {
#pragma unroll
        for (int off = 16; off >= 1; off >>= 1)
            acc[c] += __shfl_xor_sync(0xFFFFFFFF, acc[c], off);
    }
    if (lane == 0) {
#pragma unroll
        for (int c = 0; c < 6; c++) d_g[row * 8 + c] = acc[c];
    }
}

// ---------------- final: sparse agg over 6 channels + bias + log_softmax ----------------
__global__ void k_final(const float* __restrict__ b2, float* __restrict__ out) {
    int i = blockIdx.x * blockDim.x + threadIdx.x;
    if (i >= NN) return;
    float a0 = 0, a1 = 0, a2 = 0, a3 = 0, a4 = 0, a5 = 0;
    int beg = d_rp_dst[i], end = d_rp_dst[i + 1];
    int p = beg;
    for (; p + 2 <= end; p += 2) {
        int j0 = d_nb_dst[p], j1 = d_nb_dst[p + 1];
        float n0 = d_dinv[j0], n1 = d_dinv[j1];
        float4 u0 = *(const float4*)&d_g[j0 * 8];
        float2 v0 = *(const float2*)&d_g[j0 * 8 + 4];
        float4 u1 = *(const float4*)&d_g[j1 * 8];
        float2 v1 = *(const float2*)&d_g[j1 * 8 + 4];
        a0 += n0 * u0.x + n1 * u1.x;  a1 += n0 * u0.y + n1 * u1.y;
        a2 += n0 * u0.z + n1 * u1.z;  a3 += n0 * u0.w + n1 * u1.w;
        a4 += n0 * v0.x + n1 * v1.x;  a5 += n0 * v0.y + n1 * v1.y;
    }
    for (; p < end; p++) {
        int j = d_nb_dst[p];
        float nj = d_dinv[j];
        float4 u = *(const float4*)&d_g[j * 8];
        float2 v = *(const float2*)&d_g[j * 8 + 4];
        a0 += nj * u.x; a1 += nj * u.y; a2 += nj * u.z;
        a3 += nj * u.w; a4 += nj * v.x; a5 += nj * v.y;
    }
    float ni = d_dinv[i], ni2 = ni * ni;
    float4 su = *(const float4*)&d_g[i * 8];
    float2 sv = *(const float2*)&d_g[i * 8 + 4];
    float r[6];
    r[0] = ni * a0 + ni2 * su.x + b2[0];
    r[1] = ni * a1 + ni2 * su.y + b2[1];
    r[2] = ni * a2 + ni2 * su.z + b2[2];
    r[3] = ni * a3 + ni2 * su.w + b2[3];
    r[4] = ni * a4 + ni2 * sv.x + b2[4];
    r[5] = ni * a5 + ni2 * sv.y + b2[5];
    float m = r[0];
#pragma unroll
    for (int c = 1; c < 6; c++) m = fmaxf(m, r[c]);
    float s = 0.f;
#pragma unroll
    for (int c = 0; c < 6; c++) s += expf(r[c] - m);
    float l = logf(s);
#pragma unroll
    for (int c = 0; c < 6; c++) out[i * 6 + c] = r[c] - m - l;
}

// ---------------- launch ----------------
static int idx_of(const int* in_sizes, int n_in, int size, int ordinal) {
    int c = 0;
    for (int i = 0; i < n_in; i++) {
        if (in_sizes[i] == size) {
            if (c == ordinal) return i;
            c++;
        }
    }
    return 0;
}

extern "C" void kernel_launch(void* const* d_in, const int* in_sizes, int n_in,
                              void* d_out, int out_size) {
    const float* feats = (const float*)d_in[idx_of(in_sizes, n_in, NN * 512, 0)];
    const int*   e32   = (const int*)d_in[idx_of(in_sizes, n_in, 2 * EE, 0)];
    const float* W1  = (const float*)d_in[idx_of(in_sizes, n_in, 512 * 32, 0)];
    const float* b1  = (const float*)d_in[idx_of(in_sizes, n_in, 32, 0)];
    const float* W12 = (const float*)d_in[idx_of(in_sizes, n_in, 32 * 64, 0)];
    const float* b12 = (const float*)d_in[idx_of(in_sizes, n_in, 64, 0)];
    const float* W13 = (const float*)d_in[idx_of(in_sizes, n_in, 64 * 128, 0)];
    const float* b13 = (const float*)d_in[idx_of(in_sizes, n_in, 128, 0)];
    const float* W14 = (const float*)d_in[idx_of(in_sizes, n_in, 128 * 128, 1)];  // 2nd 16384
    const float* b14 = (const float*)d_in[idx_of(in_sizes, n_in, 128, 1)];        // 2nd 128
    const float* W2  = (const float*)d_in[idx_of(in_sizes, n_in, 128 * 6, 0)];
    const float* b2  = (const float*)d_in[idx_of(in_sizes, n_in, 6, 0)];
    float* out = (float*)d_out;

    // graph structure (cnt arrays are zero: static init + re-zero in k_scan)
    k_detect<<<1, 256>>>(e32);
    k_count<<<cdiv(EE, 1024), 256>>>(e32);
    k_scan<<<1, 1024>>>();
    k_fill<<<cdiv(EE, 1024), 256>>>(e32);

    // L1: bufA = feats@W1 (N,32); dense agg (A->B) + b1 + relu
    k_gemm<512, 32, 128, 32, false, false, 0, 1><<<cdiv(NN, 128), dim3(8, 32)>>>(feats, W1, nullptr);
    k_agg<32, true, 1, true><<<cdiv(NN * 32, 256), 256>>>(b1);

    // L2: dense agg at 32 (B->A), then GEMM 32->64 (A->B) + b12 + relu
    k_agg<32, false, 2, true><<<cdiv(NN * 32, 256), 256>>>(nullptr);
    k_gemm<32, 64, 64, 16, true, true, 1, 2><<<cdiv(NN, 64), dim3(16, 16)>>>(nullptr, W12, b12);

    // L3: sparse agg at 64 (B->A), then GEMM 64->128 (A->B) + b13 + relu
    k_agg<64, false, 2, false><<<cdiv(NN * 32, 256), 256>>>(nullptr);
    k_gemm<64, 128, 32, 16, true, true, 1, 2><<<cdiv(NN, 32), dim3(32, 8)>>>(nullptr, W13, b13);

    // L4: sparse agg at 128 (B->A), then GEMM 128->128 (A->B) + b14 + relu
    k_agg<128, false, 2, false><<<cdiv(NN * 32, 256), 256>>>(nullptr);
    k_gemm<128, 128, 32, 16, true, true, 1, 2><<<cdiv(NN, 32), dim3(32, 8)>>>(nullptr, W14, b14);

    // L5: GEMM 128->6 first (B -> d_g), then sparse agg at 6 + b2 + log_softmax
    k_gemm6<<<cdiv(NN * 32, 256), 256>>>(W2);
    k_final<<<cdiv(NN, 256), 256>>>(b2, out);
}

// round 9
// speedup vs baseline: 1.1761x; 1.0561x over previous
#include <cuda_runtime.h>
#include <math.h>

#define NN 12000
#define EE 400000

// ---------------- scratch (static device globals; no allocation) ----------------
// cnt arrays are zero at process start (static zero-init) and re-zeroed by
// k_scan after consumption, so every kernel_launch invocation sees zeros.
__device__ int   d_is64;           // 1 if edge_index is int64, 0 if int32
__device__ int   d_cnt_src[NN];
__device__ int   d_cnt_dst[NN];
__device__ int   d_rp_src[NN + 1];
__device__ int   d_rp_dst[NN + 1];
__device__ int   d_slot_src[EE];   // per-edge rank within src bucket (-1 = skip)
__device__ int   d_slot_dst[EE];   // per-edge rank within dst bucket (-1 = skip)
__device__ int   d_nb_src[EE];     // neighbors (dst) grouped by src, self-edges excluded
__device__ int   d_nb_dst[EE];     // neighbors (src) grouped by dst, all edges
__device__ float d_dis[NN];        // dense-path  deg^-1/2
__device__ float d_dinv[NN];       // sparse-path deg^-1/2
__device__ __align__(16) float d_bufA[NN * 128];
__device__ __align__(16) float d_bufB[NN * 128];
__device__ __align__(16) float d_g[NN * 8];   // L5 pre-agg logits, padded stride 8

static inline int cdiv(int a, int b) { return (a + b - 1) / b; }

template<int SEL>
__device__ __forceinline__ float* buf_ptr() {
    if (SEL == 1) return d_bufA;
    return d_bufB;
}

// ---------------- edge dtype detection ----------------
// View edges as int32 words; first 800000 words are in-bounds for either dtype.
// If really int64 (values < 2^31), every odd word is a zero high-word.
__global__ void k_detect(const int* __restrict__ e32) {
    __shared__ int any_nonzero;
    if (threadIdx.x == 0) any_nonzero = 0;
    __syncthreads();
    int nz = 0;
    for (int k = threadIdx.x; k < 4096; k += blockDim.x)
        if (e32[2 * k + 1] != 0) nz = 1;
    if (nz) any_nonzero = 1;
    __syncthreads();
    if (threadIdx.x == 0) d_is64 = any_nonzero ? 0 : 1;
}

// ---------------- CSR build pass 1: count + record per-edge slot ----------------
__global__ void k_count(const int* __restrict__ e32) {
    int base = (blockIdx.x * blockDim.x + threadIdx.x) * 4;
    int is64 = d_is64;
    int s[4], d[4];
#pragma unroll
    for (int k = 0; k < 4; k++) {
        int e = base + k;
        if (e < EE) {
            if (is64) { s[k] = e32[2 * e]; d[k] = e32[2 * (EE + e)]; }
            else      { s[k] = e32[e];     d[k] = e32[EE + e]; }
        } else { s[k] = -1; d[k] = -1; }
    }
    int p[4], q[4];
#pragma unroll
    for (int k = 0; k < 4; k++) {
        p[k] = ((unsigned)d[k] < NN) ? atomicAdd(&d_cnt_dst[d[k]], 1) : -1;
        q[k] = ((unsigned)s[k] < NN && s[k] != d[k]) ? atomicAdd(&d_cnt_src[s[k]], 1) : -1;
    }
#pragma unroll
    for (int k = 0; k < 4; k++) {
        int e = base + k;
        if (e < EE) { d_slot_dst[e] = p[k]; d_slot_src[e] = q[k]; }
    }
}

// single-block scan, 1024 threads, 12 contiguous elements per thread.
// Also re-zeroes cnt arrays (so the next replay starts clean).
__global__ void k_scan() {
    __shared__ int wsum[32];
    constexpr int CH = 12;  // 1024 * 12 = 12288 >= NN
    int t = threadIdx.x;
    int lane = t & 31, wid = t >> 5;
    for (int which = 0; which < 2; which++) {
        int* cnt = which ? d_cnt_dst : d_cnt_src;
        int* rp  = which ? d_rp_dst  : d_rp_src;
        float* nrm = which ? d_dinv : d_dis;

        int base = t * CH;
        int v[CH];
        int s = 0;
#pragma unroll
        for (int k = 0; k < CH; k++) {
            int i = base + k;
            int x = (i < NN) ? cnt[i] : 0;
            if (i < NN) cnt[i] = 0;    // re-zero for next invocation
            v[k] = x; s += x;
        }
        int sc = s;
#pragma unroll
        for (int off = 1; off < 32; off <<= 1) {
            int y = __shfl_up_sync(0xFFFFFFFFu, sc, off);
            if (lane >= off) sc += y;
        }
        if (lane == 31) wsum[wid] = sc;
        __syncthreads();
        if (wid == 0) {
            int ws = wsum[lane];
#pragma unroll
            for (int off = 1; off < 32; off <<= 1) {
                int y = __shfl_up_sync(0xFFFFFFFFu, ws, off);
                if (lane >= off) ws += y;
            }
            wsum[lane] = ws;
        }
        __syncthreads();
        int run = sc - s + (wid > 0 ? wsum[wid - 1] : 0);
#pragma unroll
        for (int k = 0; k < CH; k++) {
            int i = base + k;
            if (i < NN) {
                nrm[i] = rsqrtf((float)(v[k] + 1));  // +1: diag=1 (dense) / self loop (sparse)
                run += v[k];
                rp[i + 1] = run;
            }
        }
        if (t == 0) rp[0] = 0;
        __syncthreads();
    }
}

// ---------------- CSR build pass 2: place edges (NO atomics) ----------------
__global__ void k_place(const int* __restrict__ e32) {
    int base = (blockIdx.x * blockDim.x + threadIdx.x) * 4;
    int is64 = d_is64;
    int s[4], d[4], ps[4], pd[4];
#pragma unroll
    for (int k = 0; k < 4; k++) {
        int e = base + k;
        if (e < EE) {
            if (is64) { s[k] = e32[2 * e]; d[k] = e32[2 * (EE + e)]; }
            else      { s[k] = e32[e];     d[k] = e32[EE + e]; }
            pd[k] = d_slot_dst[e];
            ps[k] = d_slot_src[e];
        } else { s[k] = -1; d[k] = -1; ps[k] = -1; pd[k] = -1; }
    }
    int od[4], os[4];
#pragma unroll
    for (int k = 0; k < 4; k++) {
        od[k] = (pd[k] >= 0) ? d_rp_dst[d[k]] + pd[k] : -1;
        os[k] = (ps[k] >= 0) ? d_rp_src[s[k]] + ps[k] : -1;
    }
#pragma unroll
    for (int k = 0; k < 4; k++) {
        if (od[k] >= 0) d_nb_dst[od[k]] = s[k];
        if (os[k] >= 0) d_nb_src[os[k]] = d[k];
    }
}

// ---------------- GEMM: Y = X[N,DIN] @ W[DIN,DOUT] (+bias, +relu) ----------------
// IN_SEL: 0 = external pointer arg, 1 = d_bufA, 2 = d_bufB.  OUT_SEL: 1/2.
template<int DIN, int DOUT, int BM, int BK, bool RELU, bool BIAS, int IN_SEL, int OUT_SEL>
__global__ void k_gemm(const float* __restrict__ Xext, const float* __restrict__ W,
                       const float* __restrict__ bias) {
    const float* X = (IN_SEL == 0) ? Xext : (const float*)buf_ptr<IN_SEL>();
    float* Y = buf_ptr<OUT_SEL>();

    constexpr int TM = 4, TN = 4;
    constexpr int TX = DOUT / TN, TY = BM / TM;
    constexpr int NT = TX * TY;
    static_assert(BK % 4 == 0, "");
    __shared__ float Xs[BM][BK + 1];
    __shared__ __align__(16) float Ws[BK][DOUT];

    int tx = threadIdx.x, ty = threadIdx.y;
    int tid = ty * TX + tx;
    int row0 = blockIdx.x * BM;

    float acc[TM][TN];
#pragma unroll
    for (int i = 0; i < TM; i++)
#pragma unroll
        for (int j = 0; j < TN; j++) acc[i][j] = 0.f;

    for (int k0 = 0; k0 < DIN; k0 += BK) {
        constexpr int XF4 = BM * BK / 4;
#pragma unroll
        for (int idx = tid; idx < XF4; idx += NT) {
            int r = idx / (BK / 4), c4 = idx % (BK / 4);
            int gr = row0 + r;
            float4 xv = make_float4(0.f, 0.f, 0.f, 0.f);
            if (gr < NN) xv = *reinterpret_cast<const float4*>(&X[gr * DIN + k0 + c4 * 4]);
            Xs[r][c4 * 4 + 0] = xv.x;
            Xs[r][c4 * 4 + 1] = xv.y;
            Xs[r][c4 * 4 + 2] = xv.z;
            Xs[r][c4 * 4 + 3] = xv.w;
        }
        constexpr int WF4 = BK * DOUT / 4;
#pragma unroll
        for (int idx = tid; idx < WF4; idx += NT) {
            int r = idx / (DOUT / 4), c4 = idx % (DOUT / 4);
            *reinterpret_cast<float4*>(&Ws[r][c4 * 4]) =
                *reinterpret_cast<const float4*>(&W[(k0 + r) * DOUT + c4 * 4]);
        }
        __syncthreads();
#pragma unroll
        for (int kk = 0; kk < BK; kk++) {
            float a[TM];
#pragma unroll
            for (int i = 0; i < TM; i++) a[i] = Xs[ty * TM + i][kk];
            float4 wv = *reinterpret_cast<const float4*>(&Ws[kk][tx * TN]);
            float w[TN] = {wv.x, wv.y, wv.z, wv.w};
#pragma unroll
            for (int i = 0; i < TM; i++)
#pragma unroll
                for (int j = 0; j < TN; j++) acc[i][j] += a[i] * w[j];
        }
        __syncthreads();
    }
#pragma unroll
    for (int i = 0; i < TM; i++) {
        int gr = row0 + ty * TM + i;
        if (gr < NN) {
#pragma unroll
            for (int j = 0; j < TN; j++) {
                int c = tx * TN + j;
                float r = acc[i][j];
                if (BIAS) r += bias[c];
                if (RELU) r = fmaxf(r, 0.f);
                Y[gr * DOUT + c] = r;
            }
        }
    }
}

// ---------------- aggregation: warp per node, lane per V channels, unroll 8 ----------------
template<int D, bool BIASRELU, int IN_SEL, bool DENSE>
__global__ void k_agg(const float* __restrict__ bias) {
    const float* X = buf_ptr<IN_SEL>();
    float* Y = buf_ptr<IN_SEL == 1 ? 2 : 1>();
    const int*   rp  = DENSE ? d_rp_src : d_rp_dst;
    const int*   nb  = DENSE ? d_nb_src : d_nb_dst;
    const float* nrm = DENSE ? d_dis    : d_dinv;

    constexpr int V = D / 32;  // 1, 2 or 4
    int gw = (blockIdx.x * blockDim.x + threadIdx.x) >> 5;
    int lane = threadIdx.x & 31;
    if (gw >= NN) return;

    float acc[V];
#pragma unroll
    for (int v = 0; v < V; v++) acc[v] = 0.f;

    int beg = rp[gw], end = rp[gw + 1];
    int p = beg;
    constexpr int U = 8;
    for (; p + U <= end; p += U) {
        int j[U]; float n[U];
#pragma unroll
        for (int u = 0; u < U; u++) j[u] = nb[p + u];
#pragma unroll
        for (int u = 0; u < U; u++) n[u] = nrm[j[u]];
        if (V == 4) {
            float4 x[U];
#pragma unroll
            for (int u = 0; u < U; u++) x[u] = *(const float4*)&X[j[u] * D + lane * 4];
#pragma unroll
            for (int u = 0; u < U; u++) {
                acc[0] += n[u] * x[u].x; acc[1] += n[u] * x[u].y;
                acc[2] += n[u] * x[u].z; acc[3] += n[u] * x[u].w;
            }
        } else if (V == 2) {
            float2 x[U];
#pragma unroll
            for (int u = 0; u < U; u++) x[u] = *(const float2*)&X[j[u] * D + lane * 2];
#pragma unroll
            for (int u = 0; u < U; u++) { acc[0] += n[u] * x[u].x; acc[1] += n[u] * x[u].y; }
        } else {
            float x[U];
#pragma unroll
            for (int u = 0; u < U; u++) x[u] = X[j[u] * D + lane];
#pragma unroll
            for (int u = 0; u < U; u++) acc[0] += n[u] * x[u];
        }
    }
    for (; p < end; p++) {
        int j = nb[p];
        float nj = nrm[j];
        if (V == 4) {
            float4 x = *(const float4*)&X[j * D + lane * 4];
            acc[0] += nj * x.x; acc[1] += nj * x.y; acc[2] += nj * x.z; acc[3] += nj * x.w;
        } else if (V == 2) {
            float2 x = *(const float2*)&X[j * D + lane * 2];
            acc[0] += nj * x.x; acc[1] += nj * x.y;
        } else {
            acc[0] += nj * X[j * D + lane];
        }
    }
    float ni = nrm[gw], ni2 = ni * ni;
#pragma unroll
    for (int v = 0; v < V; v++) {
        float r = ni * acc[v] + ni2 * X[gw * D + lane * V + v];
        if (BIASRELU) r = fmaxf(r + bias[lane * V + v], 0.f);
        Y[gw * D + lane * V + v] = r;
    }
}

// ---------------- L5 GEMM: warp per row, bufB[N,128] @ W[128,6] -> d_g ----------------
__global__ void k_gemm6(const float* __restrict__ W) {
    const float* X = d_bufB;
    int row = (blockIdx.x * blockDim.x + threadIdx.x) >> 5;
    int lane = threadIdx.x & 31;
    if (row >= NN) return;
    float acc[6] = {0.f, 0.f, 0.f, 0.f, 0.f, 0.f};
#pragma unroll
    for (int kb = 0; kb < 4; kb++) {
        int k = kb * 32 + lane;
        float x = X[row * 128 + k];
#pragma unroll
        for (int c = 0; c < 6; c++) acc[c] += x * W[k * 6 + c];
    }
#pragma unroll
    for (int c = 0; c < 6; c++) {
#pragma unroll
        for (int off = 16; off >= 1; off >>= 1)
            acc[c] += __shfl_xor_sync(0xFFFFFFFF, acc[c], off);
    }
    if (lane == 0) {
#pragma unroll
        for (int c = 0; c < 6; c++) d_g[row * 8 + c] = acc[c];
    }
}

// ---------------- final: sparse agg over 6 channels + bias + log_softmax ----------------
__global__ void k_final(const float* __restrict__ b2, float* __restrict__ out) {
    int i = blockIdx.x * blockDim.x + threadIdx.x;
    if (i >= NN) return;
    float a0 = 0, a1 = 0, a2 = 0, a3 = 0, a4 = 0, a5 = 0;
    int beg = d_rp_dst[i], end = d_rp_dst[i + 1];
    int p = beg;
    for (; p + 2 <= end; p += 2) {
        int j0 = d_nb_dst[p], j1 = d_nb_dst[p + 1];
        float n0 = d_dinv[j0], n1 = d_dinv[j1];
        float4 u0 = *(const float4*)&d_g[j0 * 8];
        float2 v0 = *(const float2*)&d_g[j0 * 8 + 4];
        float4 u1 = *(const float4*)&d_g[j1 * 8];
        float2 v1 = *(const float2*)&d_g[j1 * 8 + 4];
        a0 += n0 * u0.x + n1 * u1.x;  a1 += n0 * u0.y + n1 * u1.y;
        a2 += n0 * u0.z + n1 * u1.z;  a3 += n0 * u0.w + n1 * u1.w;
        a4 += n0 * v0.x + n1 * v1.x;  a5 += n0 * v0.y + n1 * v1.y;
    }
    for (; p < end; p++) {
        int j = d_nb_dst[p];
        float nj = d_dinv[j];
        float4 u = *(const float4*)&d_g[j * 8];
        float2 v = *(const float2*)&d_g[j * 8 + 4];
        a0 += nj * u.x; a1 += nj * u.y; a2 += nj * u.z;
        a3 += nj * u.w; a4 += nj * v.x; a5 += nj * v.y;
    }
    float ni = d_dinv[i], ni2 = ni * ni;
    float4 su = *(const float4*)&d_g[i * 8];
    float2 sv = *(const float2*)&d_g[i * 8 + 4];
    float r[6];
    r[0] = ni * a0 + ni2 * su.x + b2[0];
    r[1] = ni * a1 + ni2 * su.y + b2[1];
    r[2] = ni * a2 + ni2 * su.z + b2[2];
    r[3] = ni * a3 + ni2 * su.w + b2[3];
    r[4] = ni * a4 + ni2 * sv.x + b2[4];
    r[5] = ni * a5 + ni2 * sv.y + b2[5];
    float m = r[0];
#pragma unroll
    for (int c = 1; c < 6; c++) m = fmaxf(m, r[c]);
    float s = 0.f;
#pragma unroll
    for (int c = 0; c < 6; c++) s += expf(r[c] - m);
    float l = logf(s);
#pragma unroll
    for (int c = 0; c < 6; c++) out[i * 6 + c] = r[c] - m - l;
}

// ---------------- launch ----------------
static int idx_of(const int* in_sizes, int n_in, int size, int ordinal) {
    int c = 0;
    for (int i = 0; i < n_in; i++) {
        if (in_sizes[i] == size) {
            if (c == ordinal) return i;
            c++;
        }
    }
    return 0;
}

extern "C" void kernel_launch(void* const* d_in, const int* in_sizes, int n_in,
                              void* d_out, int out_size) {
    const float* feats = (const float*)d_in[idx_of(in_sizes, n_in, NN * 512, 0)];
    const int*   e32   = (const int*)d_in[idx_of(in_sizes, n_in, 2 * EE, 0)];
    const float* W1  = (const float*)d_in[idx_of(in_sizes, n_in, 512 * 32, 0)];
    const float* b1  = (const float*)d_in[idx_of(in_sizes, n_in, 32, 0)];
    const float* W12 = (const float*)d_in[idx_of(in_sizes, n_in, 32 * 64, 0)];
    const float* b12 = (const float*)d_in[idx_of(in_sizes, n_in, 64, 0)];
    const float* W13 = (const float*)d_in[idx_of(in_sizes, n_in, 64 * 128, 0)];
    const float* b13 = (const float*)d_in[idx_of(in_sizes, n_in, 128, 0)];
    const float* W14 = (const float*)d_in[idx_of(in_sizes, n_in, 128 * 128, 1)];  // 2nd 16384
    const float* b14 = (const float*)d_in[idx_of(in_sizes, n_in, 128, 1)];        // 2nd 128
    const float* W2  = (const float*)d_in[idx_of(in_sizes, n_in, 128 * 6, 0)];
    const float* b2  = (const float*)d_in[idx_of(in_sizes, n_in, 6, 0)];
    float* out = (float*)d_out;

    // graph structure (cnt arrays are zero: static init + re-zero in k_scan)
    k_detect<<<1, 256>>>(e32);
    k_count<<<cdiv(EE, 1024), 256>>>(e32);
    k_scan<<<1, 1024>>>();
    k_place<<<cdiv(EE, 1024), 256>>>(e32);

    // L1: bufA = feats@W1 (N,32); dense agg (A->B) + b1 + relu
    k_gemm<512, 32, 128, 32, false, false, 0, 1><<<cdiv(NN, 128), dim3(8, 32)>>>(feats, W1, nullptr);
    k_agg<32, true, 1, true><<<cdiv(NN * 32, 256), 256>>>(b1);

    // L2: dense agg at 32 (B->A), then GEMM 32->64 (A->B) + b12 + relu
    k_agg<32, false, 2, true><<<cdiv(NN * 32, 256), 256>>>(nullptr);
    k_gemm<32, 64, 64, 16, true, true, 1, 2><<<cdiv(NN, 64), dim3(16, 16)>>>(nullptr, W12, b12);

    // L3: sparse agg at 64 (B->A), then GEMM 64->128 (A->B) + b13 + relu
    k_agg<64, false, 2, false><<<cdiv(NN * 32, 256), 256>>>(nullptr);
    k_gemm<64, 128, 64, 16, true, true, 1, 2><<<cdiv(NN, 64), dim3(32, 16)>>>(nullptr, W13, b13);

    // L4: sparse agg at 128 (B->A), then GEMM 128->128 (A->B) + b14 + relu
    k_agg<128, false, 2, false><<<cdiv(NN * 32, 256), 256>>>(nullptr);
    k_gemm<128, 128, 64, 16, true, true, 1, 2><<<cdiv(NN, 64), dim3(32, 16)>>>(nullptr, W14, b14);

    // L5: GEMM 128->6 first (B -> d_g), then sparse agg at 6 + b2 + log_softmax
    k_gemm6<<<cdiv(NN * 32, 256), 256>>>(W2);
    k_final<<<cdiv(NN, 256), 256>>>(b2, out);
}

// round 10
// speedup vs baseline: 1.2034x; 1.0232x over previous
#include <cuda_runtime.h>
#include <math.h>

#define NN 12000
#define EE 400000

// ---------------- scratch (static device globals; no allocation) ----------------
// cnt arrays are zero at process start (static zero-init) and re-zeroed by
// k_scan after consumption, so every kernel_launch invocation sees zeros.
__device__ int   d_cnt_src[NN];
__device__ int   d_cnt_dst[NN];
__device__ int   d_rp_src[NN + 1];
__device__ int   d_rp_dst[NN + 1];
__device__ int   d_slot_src[EE];   // per-edge rank within src bucket (-1 = skip)
__device__ int   d_slot_dst[EE];   // per-edge rank within dst bucket (-1 = skip)
__device__ int   d_nb_src[EE];     // neighbors (dst) grouped by src, self-edges excluded
__device__ int   d_nb_dst[EE];     // neighbors (src) grouped by dst, all edges
__device__ float d_dis[NN];        // dense-path  deg^-1/2
__device__ float d_dinv[NN];       // sparse-path deg^-1/2
__device__ __align__(16) float d_bufA[NN * 128];
__device__ __align__(16) float d_bufB[NN * 128];
__device__ __align__(16) float d_g[NN * 8];   // L5 pre-agg logits, padded stride 8

static inline int cdiv(int a, int b) { return (a + b - 1) / b; }

template<int SEL>
__device__ __forceinline__ float* buf_ptr() {
    if (SEL == 1) return d_bufA;
    return d_bufB;
}

// ---------------- per-block edge dtype detection ----------------
// View edges as int32 words. If really int64 (values < 2^31), every odd word is
// a zero high-word; int32 node-id data cannot have 1024 consecutive zero odd
// words. Every block evaluates the same criterion on the same words ->
// deterministic, identical verdict in all blocks, no extra launch.
__device__ __forceinline__ int block_detect_is64(const int* __restrict__ e32) {
    int nz = 0;
    for (int k = threadIdx.x; k < 1024; k += blockDim.x)
        nz |= (e32[2 * k + 1] != 0);
    return __syncthreads_or(nz) ? 0 : 1;
}

// ---------------- CSR build pass 1: count + record per-edge slot ----------------
__global__ void k_count(const int* __restrict__ e32) {
    int is64 = block_detect_is64(e32);
    int e = blockIdx.x * blockDim.x + threadIdx.x;
    if (e >= EE) return;
    int s, d;
    if (is64) { s = e32[2 * e]; d = e32[2 * (EE + e)]; }
    else      { s = e32[e];     d = e32[EE + e]; }
    int p = ((unsigned)d < NN) ? atomicAdd(&d_cnt_dst[d], 1) : -1;
    int q = ((unsigned)s < NN && s != d) ? atomicAdd(&d_cnt_src[s], 1) : -1;
    d_slot_dst[e] = p;
    d_slot_src[e] = q;
}

// single-block scan, 1024 threads, 12 contiguous elements per thread.
// Also re-zeroes cnt arrays (so the next replay starts clean).
__global__ void k_scan() {
    __shared__ int wsum[32];
    constexpr int CH = 12;  // 1024 * 12 = 12288 >= NN
    int t = threadIdx.x;
    int lane = t & 31, wid = t >> 5;
    for (int which = 0; which < 2; which++) {
        int* cnt = which ? d_cnt_dst : d_cnt_src;
        int* rp  = which ? d_rp_dst  : d_rp_src;
        float* nrm = which ? d_dinv : d_dis;

        int base = t * CH;
        int v[CH];
        int s = 0;
#pragma unroll
        for (int k = 0; k < CH; k++) {
            int i = base + k;
            int x = (i < NN) ? cnt[i] : 0;
            if (i < NN) cnt[i] = 0;    // re-zero for next invocation
            v[k] = x; s += x;
        }
        int sc = s;
#pragma unroll
        for (int off = 1; off < 32; off <<= 1) {
            int y = __shfl_up_sync(0xFFFFFFFFu, sc, off);
            if (lane >= off) sc += y;
        }
        if (lane == 31) wsum[wid] = sc;
        __syncthreads();
        if (wid == 0) {
            int ws = wsum[lane];
#pragma unroll
            for (int off = 1; off < 32; off <<= 1) {
                int y = __shfl_up_sync(0xFFFFFFFFu, ws, off);
                if (lane >= off) ws += y;
            }
            wsum[lane] = ws;
        }
        __syncthreads();
        int run = sc - s + (wid > 0 ? wsum[wid - 1] : 0);
#pragma unroll
        for (int k = 0; k < CH; k++) {
            int i = base + k;
            if (i < NN) {
                nrm[i] = rsqrtf((float)(v[k] + 1));  // +1: diag=1 (dense) / self loop (sparse)
                run += v[k];
                rp[i + 1] = run;
            }
        }
        if (t == 0) rp[0] = 0;
        __syncthreads();
    }
}

// ---------------- CSR build pass 2: place edges (NO atomics) ----------------
__global__ void k_place(const int* __restrict__ e32) {
    int is64 = block_detect_is64(e32);
    int e = blockIdx.x * blockDim.x + threadIdx.x;
    if (e >= EE) return;
    int s, d;
    if (is64) { s = e32[2 * e]; d = e32[2 * (EE + e)]; }
    else      { s = e32[e];     d = e32[EE + e]; }
    int pd = d_slot_dst[e];
    int ps = d_slot_src[e];
    if (pd >= 0) d_nb_dst[d_rp_dst[d] + pd] = s;
    if (ps >= 0) d_nb_src[d_rp_src[s] + ps] = d;
}

// ---------------- GEMM: Y = X[N,DIN] @ W[DIN,DOUT] (+bias, +relu) ----------------
// IN_SEL: 0 = external pointer arg, 1 = d_bufA, 2 = d_bufB.  OUT_SEL: 1/2.
template<int DIN, int DOUT, int BM, int BK, int TM, bool RELU, bool BIAS, int IN_SEL, int OUT_SEL>
__global__ void k_gemm(const float* __restrict__ Xext, const float* __restrict__ W,
                       const float* __restrict__ bias) {
    const float* X = (IN_SEL == 0) ? Xext : (const float*)buf_ptr<IN_SEL>();
    float* Y = buf_ptr<OUT_SEL>();

    constexpr int TN = 4;
    constexpr int TX = DOUT / TN, TY = BM / TM;
    constexpr int NT = TX * TY;
    static_assert(BK % 4 == 0, "");
    __shared__ float Xs[BM][BK + 1];
    __shared__ __align__(16) float Ws[BK][DOUT];

    int tx = threadIdx.x, ty = threadIdx.y;
    int tid = ty * TX + tx;
    int row0 = blockIdx.x * BM;

    float acc[TM][TN];
#pragma unroll
    for (int i = 0; i < TM; i++)
#pragma unroll
        for (int j = 0; j < TN; j++) acc[i][j] = 0.f;

    for (int k0 = 0; k0 < DIN; k0 += BK) {
        constexpr int XF4 = BM * BK / 4;
#pragma unroll
        for (int idx = tid; idx < XF4; idx += NT) {
            int r = idx / (BK / 4), c4 = idx % (BK / 4);
            int gr = row0 + r;
            float4 xv = make_float4(0.f, 0.f, 0.f, 0.f);
            if (gr < NN) xv = *reinterpret_cast<const float4*>(&X[gr * DIN + k0 + c4 * 4]);
            Xs[r][c4 * 4 + 0] = xv.x;
            Xs[r][c4 * 4 + 1] = xv.y;
            Xs[r][c4 * 4 + 2] = xv.z;
            Xs[r][c4 * 4 + 3] = xv.w;
        }
        constexpr int WF4 = BK * DOUT / 4;
#pragma unroll
        for (int idx = tid; idx < WF4; idx += NT) {
            int r = idx / (DOUT / 4), c4 = idx % (DOUT / 4);
            *reinterpret_cast<float4*>(&Ws[r][c4 * 4]) =
                *reinterpret_cast<const float4*>(&W[(k0 + r) * DOUT + c4 * 4]);
        }
        __syncthreads();
#pragma unroll
        for (int kk = 0; kk < BK; kk++) {
            float a[TM];
#pragma unroll
            for (int i = 0; i < TM; i++) a[i] = Xs[ty * TM + i][kk];
            float4 wv = *reinterpret_cast<const float4*>(&Ws[kk][tx * TN]);
            float w[TN] = {wv.x, wv.y, wv.z, wv.w};
#pragma unroll
            for (int i = 0; i < TM; i++)
#pragma unroll
                for (int j = 0; j < TN; j++) acc[i][j] += a[i] * w[j];
        }
        __syncthreads();
    }
#pragma unroll
    for (int i = 0; i < TM; i++) {
        int gr = row0 + ty * TM + i;
        if (gr < NN) {
#pragma unroll
            for (int j = 0; j < TN; j++) {
                int c = tx * TN + j;
                float r = acc[i][j];
                if (BIAS) r += bias[c];
                if (RELU) r = fmaxf(r, 0.f);
                Y[gr * DOUT + c] = r;
            }
        }
    }
}

// ---------------- aggregation: warp per node, lane per V channels, unroll 8 ----------------
template<int D, bool BIASRELU, int IN_SEL, bool DENSE>
__global__ void k_agg(const float* __restrict__ bias) {
    const float* X = buf_ptr<IN_SEL>();
    float* Y = buf_ptr<IN_SEL == 1 ? 2 : 1>();
    const int*   rp  = DENSE ? d_rp_src : d_rp_dst;
    const int*   nb  = DENSE ? d_nb_src : d_nb_dst;
    const float* nrm = DENSE ? d_dis    : d_dinv;

    constexpr int V = D / 32;  // 1, 2 or 4
    int gw = (blockIdx.x * blockDim.x + threadIdx.x) >> 5;
    int lane = threadIdx.x & 31;
    if (gw >= NN) return;

    float acc[V];
#pragma unroll
    for (int v = 0; v < V; v++) acc[v] = 0.f;

    int beg = rp[gw], end = rp[gw + 1];
    int p = beg;
    constexpr int U = 8;
    for (; p + U <= end; p += U) {
        int j[U]; float n[U];
#pragma unroll
        for (int u = 0; u < U; u++) j[u] = nb[p + u];
#pragma unroll
        for (int u = 0; u < U; u++) n[u] = nrm[j[u]];
        if (V == 4) {
            float4 x[U];
#pragma unroll
            for (int u = 0; u < U; u++) x[u] = *(const float4*)&X[j[u] * D + lane * 4];
#pragma unroll
            for (int u = 0; u < U; u++) {
                acc[0] += n[u] * x[u].x; acc[1] += n[u] * x[u].y;
                acc[2] += n[u] * x[u].z; acc[3] += n[u] * x[u].w;
            }
        } else if (V == 2) {
            float2 x[U];
#pragma unroll
            for (int u = 0; u < U; u++) x[u] = *(const float2*)&X[j[u] * D + lane * 2];
#pragma unroll
            for (int u = 0; u < U; u++) { acc[0] += n[u] * x[u].x; acc[1] += n[u] * x[u].y; }
        } else {
            float x[U];
#pragma unroll
            for (int u = 0; u < U; u++) x[u] = X[j[u] * D + lane];
#pragma unroll
            for (int u = 0; u < U; u++) acc[0] += n[u] * x[u];
        }
    }
    for (; p < end; p++) {
        int j = nb[p];
        float nj = nrm[j];
        if (V == 4) {
            float4 x = *(const float4*)&X[j * D + lane * 4];
            acc[0] += nj * x.x; acc[1] += nj * x.y; acc[2] += nj * x.z; acc[3] += nj * x.w;
        } else if (V == 2) {
            float2 x = *(const float2*)&X[j * D + lane * 2];
            acc[0] += nj * x.x; acc[1] += nj * x.y;
        } else {
            acc[0] += nj * X[j * D + lane];
        }
    }
    float ni = nrm[gw], ni2 = ni * ni;
#pragma unroll
    for (int v = 0; v < V; v++) {
        float r = ni * acc[v] + ni2 * X[gw * D + lane * V + v];
        if (BIASRELU) r = fmaxf(r + bias[lane * V + v], 0.f);
        Y[gw * D + lane * V + v] = r;
    }
}

// ---------------- L5 GEMM: warp per row, bufB[N,128] @ W[128,6] -> d_g ----------------
__global__ void k_gemm6(const float* __restrict__ W) {
    const float* X = d_bufB;
    int row = (blockIdx.x * blockDim.x + threadIdx.x) >> 5;
    int lane = threadIdx.x & 31;
    if (row >= NN) return;
    float acc[6] = {0.f, 0.f, 0.f, 0.f, 0.f, 0.f};
#pragma unroll
    for (int kb = 0; kb < 4; kb++) {
        int k = kb * 32 + lane;
        float x = X[row * 128 + k];
#pragma unroll
        for (int c = 0; c < 6; c++) acc[c] += x * W[k * 6 + c];
    }
#pragma unroll
    for (int c = 0; c < 6; c++) {
#pragma unroll
        for (int off = 16; off >= 1; off >>= 1)
            acc[c] += __shfl_xor_sync(0xFFFFFFFF, acc[c], off);
    }
    if (lane == 0) {
#pragma unroll
        for (int c = 0; c < 6; c++) d_g[row * 8 + c] = acc[c];
    }
}

// ---------------- final: sparse agg over 6 channels + bias + log_softmax ----------------
__global__ void k_final(const float* __restrict__ b2, float* __restrict__ out) {
    int i = blockIdx.x * blockDim.x + threadIdx.x;
    if (i >= NN) return;
    float a0 = 0, a1 = 0, a2 = 0, a3 = 0, a4 = 0, a5 = 0;
    int beg = d_rp_dst[i], end = d_rp_dst[i + 1];
    int p = beg;
    for (; p + 2 <= end; p += 2) {
        int j0 = d_nb_dst[p], j1 = d_nb_dst[p + 1];
        float n0 = d_dinv[j0], n1 = d_dinv[j1];
        float4 u0 = *(const float4*)&d_g[j0 * 8];
        float2 v0 = *(const float2*)&d_g[j0 * 8 + 4];
        float4 u1 = *(const float4*)&d_g[j1 * 8];
        float2 v1 = *(const float2*)&d_g[j1 * 8 + 4];
        a0 += n0 * u0.x + n1 * u1.x;  a1 += n0 * u0.y + n1 * u1.y;
        a2 += n0 * u0.z + n1 * u1.z;  a3 += n0 * u0.w + n1 * u1.w;
        a4 += n0 * v0.x + n1 * v1.x;  a5 += n0 * v0.y + n1 * v1.y;
    }
    for (; p < end; p++) {
        int j = d_nb_dst[p];
        float nj = d_dinv[j];
        float4 u = *(const float4*)&d_g[j * 8];
        float2 v = *(const float2*)&d_g[j * 8 + 4];
        a0 += nj * u.x; a1 += nj * u.y; a2 += nj * u.z;
        a3 += nj * u.w; a4 += nj * v.x; a5 += nj * v.y;
    }
    float ni = d_dinv[i], ni2 = ni * ni;
    float4 su = *(const float4*)&d_g[i * 8];
    float2 sv = *(const float2*)&d_g[i * 8 + 4];
    float r[6];
    r[0] = ni * a0 + ni2 * su.x + b2[0];
    r[1] = ni * a1 + ni2 * su.y + b2[1];
    r[2] = ni * a2 + ni2 * su.z + b2[2];
    r[3] = ni * a3 + ni2 * su.w + b2[3];
    r[4] = ni * a4 + ni2 * sv.x + b2[4];
    r[5] = ni * a5 + ni2 * sv.y + b2[5];
    float m = r[0];
#pragma unroll
    for (int c = 1; c < 6; c++) m = fmaxf(m, r[c]);
    float s = 0.f;
#pragma unroll
    for (int c = 0; c < 6; c++) s += expf(r[c] - m);
    float l = logf(s);
#pragma unroll
    for (int c = 0; c < 6; c++) out[i * 6 + c] = r[c] - m - l;
}

// ---------------- launch ----------------
static int idx_of(const int* in_sizes, int n_in, int size, int ordinal) {
    int c = 0;
    for (int i = 0; i < n_in; i++) {
        if (in_sizes[i] == size) {
            if (c == ordinal) return i;
            c++;
        }
    }
    return 0;
}

extern "C" void kernel_launch(void* const* d_in, const int* in_sizes, int n_in,
                              void* d_out, int out_size) {
    const float* feats = (const float*)d_in[idx_of(in_sizes, n_in, NN * 512, 0)];
    const int*   e32   = (const int*)d_in[idx_of(in_sizes, n_in, 2 * EE, 0)];
    const float* W1  = (const float*)d_in[idx_of(in_sizes, n_in, 512 * 32, 0)];
    const float* b1  = (const float*)d_in[idx_of(in_sizes, n_in, 32, 0)];
    const float* W12 = (const float*)d_in[idx_of(in_sizes, n_in, 32 * 64, 0)];
    const float* b12 = (const float*)d_in[idx_of(in_sizes, n_in, 64, 0)];
    const float* W13 = (const float*)d_in[idx_of(in_sizes, n_in, 64 * 128, 0)];
    const float* b13 = (const float*)d_in[idx_of(in_sizes, n_in, 128, 0)];
    const float* W14 = (const float*)d_in[idx_of(in_sizes, n_in, 128 * 128, 1)];  // 2nd 16384
    const float* b14 = (const float*)d_in[idx_of(in_sizes, n_in, 128, 1)];        // 2nd 128
    const float* W2  = (const float*)d_in[idx_of(in_sizes, n_in, 128 * 6, 0)];
    const float* b2  = (const float*)d_in[idx_of(in_sizes, n_in, 6, 0)];
    float* out = (float*)d_out;

    // graph structure (cnt arrays are zero: static init + re-zero in k_scan)
    k_count<<<cdiv(EE, 256), 256>>>(e32);
    k_scan<<<1, 1024>>>();
    k_place<<<cdiv(EE, 256), 256>>>(e32);

    // L1: bufA = feats@W1 (N,32); dense agg (A->B) + b1 + relu
    k_gemm<512, 32, 128, 32, 4, false, false, 0, 1><<<cdiv(NN, 128), dim3(8, 32)>>>(feats, W1, nullptr);
    k_agg<32, true, 1, true><<<cdiv(NN * 32, 256), 256>>>(b1);

    // L2: dense agg at 32 (B->A), then GEMM 32->64 (A->B) + b12 + relu
    k_agg<32, false, 2, true><<<cdiv(NN * 32, 256), 256>>>(nullptr);
    k_gemm<32, 64, 64, 16, 4, true, true, 1, 2><<<cdiv(NN, 64), dim3(16, 16)>>>(nullptr, W12, b12);

    // L3: sparse agg at 64 (B->A), then GEMM 64->128 (A->B) + b13 + relu
    k_agg<64, false, 2, false><<<cdiv(NN * 32, 256), 256>>>(nullptr);
    k_gemm<64, 128, 64, 16, 8, true, true, 1, 2><<<cdiv(NN, 64), dim3(32, 8)>>>(nullptr, W13, b13);

    // L4: sparse agg at 128 (B->A), then GEMM 128->128 (A->B) + b14 + relu
    k_agg<128, false, 2, false><<<cdiv(NN * 32, 256), 256>>>(nullptr);
    k_gemm<128, 128, 64, 16, 8, true, true, 1, 2><<<cdiv(NN, 64), dim3(32, 8)>>>(nullptr, W14, b14);

    // L5: GEMM 128->6 first (B -> d_g), then sparse agg at 6 + b2 + log_softmax
    k_gemm6<<<cdiv(NN * 32, 256), 256>>>(W2);
    k_final<<<cdiv(NN, 256), 256>>>(b2, out);
}